// round 3
// baseline (speedup 1.0000x reference)
#include <cuda_runtime.h>
#include <cuda_bf16.h>

typedef unsigned long long u64;

// ---------------- packed f32x2 helpers ----------------
__device__ __forceinline__ u64 fma2(u64 a, u64 b, u64 c) {
    u64 d;
    asm("fma.rn.f32x2 %0, %1, %2, %3;" : "=l"(d) : "l"(a), "l"(b), "l"(c));
    return d;
}
__device__ __forceinline__ u64 mul2(u64 a, u64 b) {
    u64 d;
    asm("mul.rn.f32x2 %0, %1, %2;" : "=l"(d) : "l"(a), "l"(b));
    return d;
}
__device__ __forceinline__ u64 add2(u64 a, u64 b) {
    u64 d;
    asm("add.rn.f32x2 %0, %1, %2;" : "=l"(d) : "l"(a), "l"(b));
    return d;
}
__device__ __forceinline__ u64 pack2(float x, float y) {
    u64 r;
    asm("mov.b64 %0, {%1, %2};" : "=l"(r) : "f"(x), "f"(y));
    return r;
}
__device__ __forceinline__ void unpack2(u64 v, float& x, float& y) {
    asm("mov.b64 {%0, %1}, %2;" : "=f"(x), "=f"(y) : "l"(v));
}
__device__ __forceinline__ u64 dup2(float f) {
    unsigned u = __float_as_uint(f);
    return ((u64)u << 32) | (u64)u;
}

// ---------------- packed activation ----------------
// act(x) = logistic^2( cos(x)*0.5 + 0.5 ),  logistic(u) = R*u*(1-u), R=3.82843
// cos via: q = round(x/pi) (magic-number trick), r = x - q*pi (2-term split),
// cos(x) = (-1)^q * cospoly(r), r in [-pi/2, pi/2].
__device__ __forceinline__ u64 act2(u64 v) {
    const u64 INVPI  = dup2(0.31830988618379067f);
    const u64 MAGIC  = dup2(12582912.0f);          // 1.5 * 2^23
    const u64 NMAGIC = dup2(-12582912.0f);
    const u64 NPIHI  = dup2(-3.14159274101257324f); // -(float)pi
    const u64 PMID   = dup2(8.742277657347586e-8f); // (float)pi - pi (back-correction)
    const u64 ONE    = dup2(1.0f);
    const u64 NONE   = dup2(-1.0f);
    const u64 HALF   = dup2(0.5f);
    const u64 NHALF  = dup2(-0.5f);
    const u64 C8     = dup2(2.443315711809948e-5f);
    const u64 C6     = dup2(-1.388731625493765e-3f);
    const u64 C4     = dup2(4.166664568298827e-2f);
    const u64 RR     = dup2(3.82843f);

    // round-to-nearest integer multiple of pi
    u64 m = fma2(v, INVPI, MAGIC);      // integer q encoded in low mantissa bits
    u64 q = add2(m, NMAGIC);            // q as float
    u64 r = fma2(q, NPIHI, v);
    r = fma2(q, PMID, r);               // r = v - q*pi, |r| <= pi/2

    u64 s = mul2(r, r);
    u64 p = fma2(s, C8, C6);
    p = fma2(s, p, C4);
    u64 t = fma2(s, NHALF, ONE);        // 1 - s/2
    u64 s2 = mul2(s, s);
    u64 c = fma2(s2, p, t);             // cos(r)

    // sign flip when q is odd: bit0 of each 32-bit half of m -> bit31
    u64 par = (m << 31) & 0x8000000080000000ULL;
    c ^= par;

    // squash into [0,1]
    u64 u = fma2(c, HALF, HALF);
    // two logistic iterations
    u64 om = fma2(u, NONE, ONE);
    u = mul2(mul2(u, om), RR);
    om = fma2(u, NONE, ONE);
    u = mul2(mul2(u, om), RR);
    return u;
}

// ---------------- shared layout (u64 units) ----------------
#define TPB 256
#define PPB 512           // points per block (2 per thread)
#define HS_OFF   0        // [64][256] u64  -> 16384
#define WD2_OFF  16384    // [64][64]       -> 4096   (k-major, dup'd)
#define WD3_OFF  20480    // [64][64]       -> 4096
#define W1_OFF   24576    // [64][2]        -> 128
#define W4_OFF   24704    // [64]           -> 64
#define B1_OFF   24768    // 64
#define B2_OFF   24832    // 64
#define B3_OFF   24896    // 64
#define B4_OFF   24960    // 1
#define SMEM_U64 24961
#define SMEM_BYTES (SMEM_U64 * 8)

// One 64->64 layer: reads hs columns (thread-private), writes them back after
// buffering activated outputs in registers. No cross-thread sharing -> no bar.
__device__ __forceinline__ void layer64(const u64* __restrict__ wd,
                                        const u64* __restrict__ bd,
                                        u64* __restrict__ hs, int tid) {
    u64 hout[64];
#pragma unroll
    for (int jt = 0; jt < 4; ++jt) {
        u64 acc[16];
#pragma unroll
        for (int j = 0; j < 16; ++j) acc[j] = bd[jt * 16 + j];
        const u64* wp = wd + jt * 16;
#pragma unroll 4
        for (int k = 0; k < 64; ++k) {
            u64 hk = hs[k * TPB + tid];
            const ulonglong2* wrow = (const ulonglong2*)(wp + k * 64);
#pragma unroll
            for (int j2 = 0; j2 < 8; ++j2) {
                ulonglong2 w = wrow[j2];
                acc[2 * j2]     = fma2(hk, w.x, acc[2 * j2]);
                acc[2 * j2 + 1] = fma2(hk, w.y, acc[2 * j2 + 1]);
            }
        }
#pragma unroll
        for (int j = 0; j < 16; ++j) hout[jt * 16 + j] = act2(acc[j]);
    }
#pragma unroll
    for (int j = 0; j < 64; ++j) hs[j * TPB + tid] = hout[j];
}

__global__ void __launch_bounds__(TPB, 1)
mlp_kernel(const float* __restrict__ x,
           const float* __restrict__ W1, const float* __restrict__ b1,
           const float* __restrict__ W2, const float* __restrict__ b2,
           const float* __restrict__ W3, const float* __restrict__ b3,
           const float* __restrict__ W4, const float* __restrict__ b4,
           float* __restrict__ out, int N) {
    extern __shared__ u64 sm[];
    const int tid = threadIdx.x;

    // ---- stage weights (transpose + duplicate into f32x2 pairs) ----
    for (int idx = tid; idx < 4096; idx += TPB) {
        int k = idx >> 6, j = idx & 63;
        sm[WD2_OFF + idx] = dup2(W2[j * 64 + k]);
        sm[WD3_OFF + idx] = dup2(W3[j * 64 + k]);
    }
    if (tid < 128) sm[W1_OFF + tid] = dup2(W1[tid]);
    if (tid < 64) {
        sm[W4_OFF + tid] = dup2(W4[tid]);
        sm[B1_OFF + tid] = dup2(b1[tid]);
        sm[B2_OFF + tid] = dup2(b2[tid]);
        sm[B3_OFF + tid] = dup2(b3[tid]);
    }
    if (tid == 0) sm[B4_OFF] = dup2(b4[0]);
    __syncthreads();

    u64* hs = sm + HS_OFF;

    const int i0 = blockIdx.x * PPB + tid;
    const int i1 = i0 + TPB;
    const bool v0 = i0 < N, v1 = i1 < N;

    float2 xa = v0 ? ((const float2*)x)[i0] : make_float2(0.f, 0.f);
    float2 xb = v1 ? ((const float2*)x)[i1] : make_float2(0.f, 0.f);
    u64 xp0 = pack2(xa.x, xb.x);
    u64 xp1 = pack2(xa.y, xb.y);

    // ---- layer 1: 2 -> 64 ----
    {
        const u64* w1d = sm + W1_OFF;
        const u64* b1d = sm + B1_OFF;
#pragma unroll 4
        for (int j = 0; j < 64; ++j) {
            u64 p = fma2(xp0, w1d[2 * j], fma2(xp1, w1d[2 * j + 1], b1d[j]));
            hs[j * TPB + tid] = act2(p);
        }
    }

    // ---- layers 2, 3: 64 -> 64 ----
    layer64(sm + WD2_OFF, sm + B2_OFF, hs, tid);
    layer64(sm + WD3_OFF, sm + B3_OFF, hs, tid);

    // ---- layer 4: 64 -> 1 ----
    {
        const u64* w4d = sm + W4_OFF;
        u64 a0 = sm[B4_OFF], a1 = dup2(0.f), a2 = dup2(0.f), a3 = dup2(0.f);
#pragma unroll 8
        for (int k = 0; k < 64; k += 4) {
            a0 = fma2(hs[(k + 0) * TPB + tid], w4d[k + 0], a0);
            a1 = fma2(hs[(k + 1) * TPB + tid], w4d[k + 1], a1);
            a2 = fma2(hs[(k + 2) * TPB + tid], w4d[k + 2], a2);
            a3 = fma2(hs[(k + 3) * TPB + tid], w4d[k + 3], a3);
        }
        u64 acc = add2(add2(a0, a1), add2(a2, a3));
        u64 o = act2(acc);
        float oa, ob;
        unpack2(o, oa, ob);
        if (v0) out[i0] = oa;
        if (v1) out[i1] = ob;
    }
}

extern "C" void kernel_launch(void* const* d_in, const int* in_sizes, int n_in,
                              void* d_out, int out_size) {
    const float* x  = (const float*)d_in[0];
    const float* W1 = (const float*)d_in[1];
    const float* b1 = (const float*)d_in[2];
    const float* W2 = (const float*)d_in[3];
    const float* b2 = (const float*)d_in[4];
    const float* W3 = (const float*)d_in[5];
    const float* b3 = (const float*)d_in[6];
    const float* W4 = (const float*)d_in[7];
    const float* b4 = (const float*)d_in[8];
    float* out = (float*)d_out;

    int N = in_sizes[0] / 2;
    int grid = (N + PPB - 1) / PPB;

    cudaFuncSetAttribute(mlp_kernel, cudaFuncAttributeMaxDynamicSharedMemorySize,
                         SMEM_BYTES);
    mlp_kernel<<<grid, TPB, SMEM_BYTES>>>(x, W1, b1, W2, b2, W3, b3, W4, b4,
                                          out, N);
}

// round 4
// speedup vs baseline: 2.4230x; 2.4230x over previous
#include <cuda_runtime.h>
#include <cuda_bf16.h>

typedef unsigned long long u64;

// ---------------- packed f32x2 helpers ----------------
__device__ __forceinline__ u64 fma2(u64 a, u64 b, u64 c) {
    u64 d;
    asm("fma.rn.f32x2 %0, %1, %2, %3;" : "=l"(d) : "l"(a), "l"(b), "l"(c));
    return d;
}
__device__ __forceinline__ u64 mul2(u64 a, u64 b) {
    u64 d;
    asm("mul.rn.f32x2 %0, %1, %2;" : "=l"(d) : "l"(a), "l"(b));
    return d;
}
__device__ __forceinline__ u64 add2(u64 a, u64 b) {
    u64 d;
    asm("add.rn.f32x2 %0, %1, %2;" : "=l"(d) : "l"(a), "l"(b));
    return d;
}
__device__ __forceinline__ u64 pack2(float x, float y) {
    u64 r;
    asm("mov.b64 %0, {%1, %2};" : "=l"(r) : "f"(x), "f"(y));
    return r;
}
__device__ __forceinline__ void unpack2(u64 v, float& x, float& y) {
    asm("mov.b64 {%0, %1}, %2;" : "=f"(x), "=f"(y) : "l"(v));
}
__device__ __forceinline__ u64 dup2(float f) {
    unsigned u = __float_as_uint(f);
    return ((u64)u << 32) | (u64)u;
}

#define R_CONST 3.82843f

// ---------------- packed activation ----------------
// act(x) = logistic^2( cos(x)*0.5 + 0.5 ),  logistic(u) = R*u*(1-u)
// FOLD_R==0: the final multiply by R is folded into the NEXT layer's weights.
template <int FOLD_R>
__device__ __forceinline__ u64 act2_t(u64 v) {
    const u64 INVPI  = dup2(0.31830988618379067f);
    const u64 MAGIC  = dup2(12582912.0f);          // 1.5 * 2^23
    const u64 NMAGIC = dup2(-12582912.0f);
    const u64 NPIHI  = dup2(-3.14159274101257324f);
    const u64 PMID   = dup2(8.742277657347586e-8f);
    const u64 ONE    = dup2(1.0f);
    const u64 NONE   = dup2(-1.0f);
    const u64 HALF   = dup2(0.5f);
    const u64 NHALF  = dup2(-0.5f);
    const u64 C8     = dup2(2.443315711809948e-5f);
    const u64 C6     = dup2(-1.388731625493765e-3f);
    const u64 C4     = dup2(4.166664568298827e-2f);
    const u64 RR     = dup2(R_CONST);

    // round to nearest multiple of pi
    u64 m = fma2(v, INVPI, MAGIC);
    u64 q = add2(m, NMAGIC);
    u64 r = fma2(q, NPIHI, v);
    r = fma2(q, PMID, r);            // r = v - q*pi, |r| <= pi/2

    u64 s = mul2(r, r);
    u64 p = fma2(s, C8, C6);
    p = fma2(s, p, C4);
    u64 t = fma2(s, NHALF, ONE);
    u64 s2 = mul2(s, s);
    u64 c = fma2(s2, p, t);          // cos(r)

    u64 par = (m << 31) & 0x8000000080000000ULL;  // parity sign of q
    c ^= par;

    u64 u = fma2(c, HALF, HALF);     // into [0,1]
    // iteration 1 (full R)
    u64 om = fma2(u, NONE, ONE);
    u = mul2(mul2(u, om), RR);
    // iteration 2 (R folded out when FOLD_R==0)
    om = fma2(u, NONE, ONE);
    u = mul2(u, om);
    if (FOLD_R) u = mul2(u, RR);
    return u;
}

// ---------------- shared layout (u64 units) ----------------
#define TPB 256
#define PPB 512
#define HS_OFF    0        // float2[64][256]  -> 16384 u64
#define WP2_OFF   16384    // u64[64][32] j-pairs, R-scaled -> 2048
#define WP3_OFF   18432    // 2048
#define W1X0_OFF  20480    // 32 (pairs of W1[:,0])
#define W1X1_OFF  20512    // 32 (pairs of W1[:,1])
#define W4D_OFF   20544    // 64 (dup'd, R-scaled)
#define B1P_OFF   20608    // 32 j-pairs
#define B2P_OFF   20640    // 32
#define B3P_OFF   20672    // 32
#define B4D_OFF   20704    // 1
#define SMEM_U64  20705
#define SMEM_BYTES (SMEM_U64 * 8)

// One 64->64 layer, output-pair packing.
// wp: u64[k=64][jp=32] = (R*W[2jp][k], R*W[2jp+1][k]) of the CURRENT layer
// (R-scaling belongs to the previous activation's folded constant).
// bp: u64[32] = (b[2jp], b[2jp+1]).
// hsF: float2 per (k,tid): (.x = point A, .y = point B)
__device__ __forceinline__ void layerB(const u64* __restrict__ wp,
                                       const u64* __restrict__ bp,
                                       float2* __restrict__ hsF, int tid) {
    u64 hout[64];  // [tile][0..15]=A-pairs, [tile][16..31]=B-pairs
#pragma unroll
    for (int t = 0; t < 2; ++t) {
        u64 accA[16], accB[16];
#pragma unroll
        for (int p = 0; p < 16; ++p) { accA[p] = bp[t * 16 + p]; accB[p] = accA[p]; }
#pragma unroll 4
        for (int k = 0; k < 64; ++k) {
            float2 h = hsF[k * TPB + tid];
            u64 dA = pack2(h.x, h.x);
            u64 dB = pack2(h.y, h.y);
            const ulonglong2* wr = (const ulonglong2*)(wp + k * 32 + t * 16);
#pragma unroll
            for (int p2 = 0; p2 < 8; ++p2) {
                ulonglong2 w = wr[p2];
                accA[2 * p2]     = fma2(dA, w.x, accA[2 * p2]);
                accB[2 * p2]     = fma2(dB, w.x, accB[2 * p2]);
                accA[2 * p2 + 1] = fma2(dA, w.y, accA[2 * p2 + 1]);
                accB[2 * p2 + 1] = fma2(dB, w.y, accB[2 * p2 + 1]);
            }
        }
#pragma unroll
        for (int p = 0; p < 16; ++p) {
            hout[t * 32 + p]      = act2_t<0>(accA[p]);
            hout[t * 32 + 16 + p] = act2_t<0>(accB[p]);
        }
    }
    // writeback: convert (j,j+1)-pairs back to (A,B) scalar float2 per j
#pragma unroll
    for (int jp = 0; jp < 32; ++jp) {
        int t = jp >> 4, p = jp & 15;
        float a0, a1, b0, b1;
        unpack2(hout[t * 32 + p], a0, a1);
        unpack2(hout[t * 32 + 16 + p], b0, b1);
        hsF[(2 * jp) * TPB + tid]     = make_float2(a0, b0);
        hsF[(2 * jp + 1) * TPB + tid] = make_float2(a1, b1);
    }
}

__global__ void __launch_bounds__(TPB, 1)
mlp_kernel(const float* __restrict__ x,
           const float* __restrict__ W1, const float* __restrict__ b1,
           const float* __restrict__ W2, const float* __restrict__ b2,
           const float* __restrict__ W3, const float* __restrict__ b3,
           const float* __restrict__ W4, const float* __restrict__ b4,
           float* __restrict__ out, int N) {
    extern __shared__ u64 sm[];
    const int tid = threadIdx.x;

    // ---- stage weights: j-pair packing, R folded into W2/W3/W4 ----
    for (int idx = tid; idx < 2048; idx += TPB) {
        int k = idx >> 5, jp = idx & 31;
        sm[WP2_OFF + idx] = pack2(R_CONST * W2[(2 * jp) * 64 + k],
                                  R_CONST * W2[(2 * jp + 1) * 64 + k]);
        sm[WP3_OFF + idx] = pack2(R_CONST * W3[(2 * jp) * 64 + k],
                                  R_CONST * W3[(2 * jp + 1) * 64 + k]);
    }
    if (tid < 32) {
        sm[W1X0_OFF + tid] = pack2(W1[(2 * tid) * 2 + 0], W1[(2 * tid + 1) * 2 + 0]);
        sm[W1X1_OFF + tid] = pack2(W1[(2 * tid) * 2 + 1], W1[(2 * tid + 1) * 2 + 1]);
        sm[B1P_OFF + tid] = pack2(b1[2 * tid], b1[2 * tid + 1]);
        sm[B2P_OFF + tid] = pack2(b2[2 * tid], b2[2 * tid + 1]);
        sm[B3P_OFF + tid] = pack2(b3[2 * tid], b3[2 * tid + 1]);
    }
    if (tid < 64) sm[W4D_OFF + tid] = dup2(R_CONST * W4[tid]);
    if (tid == 0) sm[B4D_OFF] = dup2(b4[0]);
    __syncthreads();

    float2* hsF = (float2*)(sm + HS_OFF);
    const u64* hsU = sm + HS_OFF;

    const int i0 = blockIdx.x * PPB + tid;
    const int i1 = i0 + TPB;
    const bool v0 = i0 < N, v1 = i1 < N;

    float2 xa = v0 ? ((const float2*)x)[i0] : make_float2(0.f, 0.f);
    float2 xb = v1 ? ((const float2*)x)[i1] : make_float2(0.f, 0.f);

    // ---- layer 1: 2 -> 64 (output-pair packed, outer R folded into W2) ----
    {
        u64 dA0 = pack2(xa.x, xa.x), dA1 = pack2(xa.y, xa.y);
        u64 dB0 = pack2(xb.x, xb.x), dB1 = pack2(xb.y, xb.y);
        const u64* w0 = sm + W1X0_OFF;
        const u64* w1 = sm + W1X1_OFF;
        const u64* bp = sm + B1P_OFF;
#pragma unroll 8
        for (int jp = 0; jp < 32; ++jp) {
            u64 pA = fma2(dA0, w0[jp], fma2(dA1, w1[jp], bp[jp]));
            u64 pB = fma2(dB0, w0[jp], fma2(dB1, w1[jp], bp[jp]));
            u64 aA = act2_t<0>(pA);
            u64 aB = act2_t<0>(pB);
            float a0, a1, b0, b1;
            unpack2(aA, a0, a1);
            unpack2(aB, b0, b1);
            hsF[(2 * jp) * TPB + tid]     = make_float2(a0, b0);
            hsF[(2 * jp + 1) * TPB + tid] = make_float2(a1, b1);
        }
    }

    // ---- layers 2, 3: 64 -> 64 ----
    layerB(sm + WP2_OFF, sm + B2P_OFF, hsF, tid);
    layerB(sm + WP3_OFF, sm + B3P_OFF, hsF, tid);

    // ---- layer 4: 64 -> 1 (hs float2 is already points-packed) ----
    {
        const u64* w4d = sm + W4D_OFF;
        u64 a0 = sm[B4D_OFF], a1 = dup2(0.f), a2 = dup2(0.f), a3 = dup2(0.f);
#pragma unroll 8
        for (int k = 0; k < 64; k += 4) {
            a0 = fma2(hsU[(k + 0) * TPB + tid], w4d[k + 0], a0);
            a1 = fma2(hsU[(k + 1) * TPB + tid], w4d[k + 1], a1);
            a2 = fma2(hsU[(k + 2) * TPB + tid], w4d[k + 2], a2);
            a3 = fma2(hsU[(k + 3) * TPB + tid], w4d[k + 3], a3);
        }
        u64 acc = add2(add2(a0, a1), add2(a2, a3));
        u64 o = act2_t<1>(acc);   // final activation keeps its R
        float oa, ob;
        unpack2(o, oa, ob);
        if (v0) out[i0] = oa;
        if (v1) out[i1] = ob;
    }
}

extern "C" void kernel_launch(void* const* d_in, const int* in_sizes, int n_in,
                              void* d_out, int out_size) {
    const float* x  = (const float*)d_in[0];
    const float* W1 = (const float*)d_in[1];
    const float* b1 = (const float*)d_in[2];
    const float* W2 = (const float*)d_in[3];
    const float* b2 = (const float*)d_in[4];
    const float* W3 = (const float*)d_in[5];
    const float* b3 = (const float*)d_in[6];
    const float* W4 = (const float*)d_in[7];
    const float* b4 = (const float*)d_in[8];
    float* out = (float*)d_out;

    int N = in_sizes[0] / 2;
    int grid = (N + PPB - 1) / PPB;

    cudaFuncSetAttribute(mlp_kernel, cudaFuncAttributeMaxDynamicSharedMemorySize,
                         SMEM_BYTES);
    mlp_kernel<<<grid, TPB, SMEM_BYTES>>>(x, W1, b1, W2, b2, W3, b3, W4, b4,
                                          out, N);
}